// round 4
// baseline (speedup 1.0000x reference)
#include <cuda_runtime.h>
#include <cstdint>

// QuantumParity analytic reduction:
//   features = all contiguous-range cosine products prod_{q=s..j} cos(x_q),
//   0<=s<=j<=7 (36 ranges);  out[c] = b[c] + sum_f W[c][f]*feat_f.
//
// R4: 2 threads per row, branch-free half-split by range-start parity.
//   half 0: ranges starting at s in {0,2,4,6} (20 features)
//   half 1: ranges starting at s in {1,3,5,7} (16 features + 4 zero-pads)
// Both halves run IDENTICAL code (4 chains of length 8,6,4,2) on cos values
// shifted by `half` and a W table offset by half*20 (pads have W=0).
// Combine with one 64-bit shfl.xor(16). Doubles occupancy (8192 warps,
// ~55/SM, single wave). Per-warp smem W copy + __syncwarp (no block barrier).

#define NQ 8
#define NFEAT 36
#define SLOTS 41          // 40 packed W slots + 1 bias slot
#define ROWS_PER_BLOCK 128

// Packed-slot -> original feature index (-1 = zero pad).
// Layout: [half0: chain0 p0..p7 | chain1 p0..p5 | chain2 p0..p3 | chain3 p0..p1]
//         [half1: same shape]
static __device__ const signed char kWIdx[40] = {
    0, 1, 2, 3, 4, 5, 6, 7,   15, 16, 17, 18, 19, 20,   26, 27, 28, 29,   33, 34,
    8, 9, 10, 11, 12, 13, 14, -1,  21, 22, 23, 24, 25, -1,  30, 31, 32, -1,  35, -1
};

__device__ __forceinline__ uint64_t pack_dup(float v) {
    uint64_t r;
    asm("mov.b64 %0, {%1, %1};" : "=l"(r) : "f"(v));
    return r;
}
__device__ __forceinline__ uint64_t fma2(uint64_t a, uint64_t b, uint64_t c) {
    uint64_t d;
    asm("fma.rn.f32x2 %0, %1, %2, %3;" : "=l"(d) : "l"(a), "l"(b), "l"(c));
    return d;
}
__device__ __forceinline__ uint64_t mul2(uint64_t a, uint64_t b) {
    uint64_t d;
    asm("mul.rn.f32x2 %0, %1, %2;" : "=l"(d) : "l"(a), "l"(b));
    return d;
}
__device__ __forceinline__ uint64_t add2(uint64_t a, uint64_t b) {
    uint64_t d;
    asm("add.rn.f32x2 %0, %1, %2;" : "=l"(d) : "l"(a), "l"(b));
    return d;
}
__device__ __forceinline__ uint64_t lds64(uint32_t addr) {
    uint64_t d;
    asm("ld.shared.b64 %0, [%1];" : "=l"(d) : "r"(addr));
    return d;
}

__device__ __forceinline__ float cos_poly(float x) {
    // x in [0, pi]; cos(x) = -sin(x - pi/2). Degree-9 Taylor, |err| < 2.8e-6.
    float t = x - 1.57079632679489662f;
    float u = t * t;
    float p = fmaf(u, 2.75573192e-6f, -1.98412698e-4f);
    p = fmaf(u, p, 8.33333333e-3f);
    p = fmaf(u, p, -1.66666667e-1f);
    p = fmaf(u, p, 1.0f);
    return -t * p;
}

__global__ void __launch_bounds__(256, 7)
quantum_parity_kernel(const float* __restrict__ x,
                      const float* __restrict__ W,
                      const float* __restrict__ bias,
                      float* __restrict__ out,
                      int nrows) {
    __shared__ float2 sW[8][SLOTS];   // per-warp copy: no block barrier needed
    int tid  = threadIdx.x;
    int lane = tid & 31;
    int wid  = tid >> 5;
    int half = lane >> 4;
    int row  = blockIdx.x * ROWS_PER_BLOCK + wid * 16 + (lane & 15);
    int rl   = row < nrows ? row : (nrows - 1);

    // Start the x load immediately.
    const float4* xp = reinterpret_cast<const float4*>(x) + (size_t)rl * 2;
    float4 a = xp[0];
    float4 d = xp[1];

    // Per-warp W fill (entries lane and lane+32), in flight during cos math.
    float2* wsm = sW[wid];
#pragma unroll
    for (int e = lane; e < SLOTS; e += 32) {
        float lo, hi;
        if (e == 40) { lo = bias[0]; hi = bias[1]; }
        else {
            int idx = kWIdx[e];
            if (idx >= 0) { lo = W[idx]; hi = W[NFEAT + idx]; }
            else          { lo = 0.0f;   hi = 0.0f; }
        }
        wsm[e] = make_float2(lo, hi);
    }

    // Shifted cos inputs: half 0 uses x[k], half 1 uses x[k+1] (k=7: dummy).
    float t0 = half ? a.y : a.x;
    float t1 = half ? a.z : a.y;
    float t2 = half ? a.w : a.z;
    float t3 = half ? d.x : a.w;
    float t4 = half ? d.y : d.x;
    float t5 = half ? d.z : d.y;
    float t6 = half ? d.w : d.z;
    float t7 = d.w;  // half1 pad: cos computed but W=0 kills it

    uint64_t c0 = pack_dup(cos_poly(t0));
    uint64_t c1 = pack_dup(cos_poly(t1));
    uint64_t c2 = pack_dup(cos_poly(t2));
    uint64_t c3 = pack_dup(cos_poly(t3));
    uint64_t c4 = pack_dup(cos_poly(t4));
    uint64_t c5 = pack_dup(cos_poly(t5));
    uint64_t c6 = pack_dup(cos_poly(t6));
    uint64_t c7 = pack_dup(cos_poly(t7));

    __syncwarp();

    uint32_t wbase = (uint32_t)__cvta_generic_to_shared(wsm);
    uint32_t wb = wbase + (uint32_t)half * 160;   // 20 slots * 8B per half

    uint64_t bz = lds64(wbase + 320);             // bias pair (slot 40)
    uint64_t acc0 = half ? 0ull : bz;             // bias counted once per pair
    uint64_t acc1 = 0ull;

    // 4 independent chains (lengths 8,6,4,2), slots packed consecutively.
    // chain0: c0..c7, slots 0..7
    uint64_t q0 = c0;
    acc0 = fma2(lds64(wb + 0), q0, acc0);
    // chain1: c2..c7, slots 8..13
    uint64_t q1 = c2;
    acc1 = fma2(lds64(wb + 64), q1, acc1);
    // chain2: c4..c7, slots 14..17
    uint64_t q2 = c4;
    acc0 = fma2(lds64(wb + 112), q2, acc0);
    // chain3: c6..c7, slots 18..19
    uint64_t q3 = c6;
    acc1 = fma2(lds64(wb + 144), q3, acc1);

    q0 = mul2(q0, c1); acc0 = fma2(lds64(wb + 8),   q0, acc0);
    q1 = mul2(q1, c3); acc1 = fma2(lds64(wb + 72),  q1, acc1);
    q2 = mul2(q2, c5); acc0 = fma2(lds64(wb + 120), q2, acc0);
    q3 = mul2(q3, c7); acc1 = fma2(lds64(wb + 152), q3, acc1);

    q0 = mul2(q0, c2); acc0 = fma2(lds64(wb + 16),  q0, acc0);
    q1 = mul2(q1, c4); acc1 = fma2(lds64(wb + 80),  q1, acc1);
    q2 = mul2(q2, c6); acc0 = fma2(lds64(wb + 128), q2, acc0);

    q0 = mul2(q0, c3); acc0 = fma2(lds64(wb + 24),  q0, acc0);
    q1 = mul2(q1, c5); acc1 = fma2(lds64(wb + 88),  q1, acc1);
    q2 = mul2(q2, c7); acc0 = fma2(lds64(wb + 136), q2, acc0);

    q0 = mul2(q0, c4); acc0 = fma2(lds64(wb + 32),  q0, acc0);
    q1 = mul2(q1, c6); acc1 = fma2(lds64(wb + 96),  q1, acc1);

    q0 = mul2(q0, c5); acc0 = fma2(lds64(wb + 40),  q0, acc0);
    q1 = mul2(q1, c7); acc1 = fma2(lds64(wb + 104), q1, acc1);

    q0 = mul2(q0, c6); acc0 = fma2(lds64(wb + 48),  q0, acc0);
    q0 = mul2(q0, c7); acc0 = fma2(lds64(wb + 56),  q0, acc0);

    uint64_t r = add2(acc0, acc1);

    // Combine the two halves of each row pair (lane ^ 16).
    unsigned long long rv =
        __shfl_xor_sync(0xffffffffu, (unsigned long long)r, 16);
    r = add2(r, (uint64_t)rv);

    if (half == 0 && row < nrows)
        reinterpret_cast<uint64_t*>(out)[row] = r;
}

extern "C" void kernel_launch(void* const* d_in, const int* in_sizes, int n_in,
                              void* d_out, int out_size) {
    const float* x    = (const float*)d_in[0];   // (B, 8) fp32
    const float* W    = (const float*)d_in[1];   // (2, 36) fp32
    const float* bias = (const float*)d_in[2];   // (2,) fp32

    int nrows = in_sizes[0] / NQ;                // 131072
    float* out = (float*)d_out;                  // (B, 2) fp32

    int grid = (nrows + ROWS_PER_BLOCK - 1) / ROWS_PER_BLOCK;  // 1024
    quantum_parity_kernel<<<grid, 256>>>(x, W, bias, out, nrows);
}

// round 5
// speedup vs baseline: 1.2977x; 1.2977x over previous
#include <cuda_runtime.h>
#include <cstdint>

// QuantumParity analytic reduction (see R1):
//   feat_k     = prod_{q=0..k}   cos(x_q)
//   feat_(i,j) = prod_{q=i+1..j} cos(x_q)
//   out[c] = b[c] + sum_f W[c][f] * feat_f
//
// R5: 2 rows per thread (grid halved to 256 CTAs). Amortizes the cold-load
// latency, barrier, prologue and W LDS traffic over 2 rows: each W slot is
// loaded from shared ONCE and used by both rows' packed fma2 chains.

#define NQ 8
#define NFEAT 36
#define RPT 2          // rows per thread

__device__ __forceinline__ uint64_t pack_dup(float v) {
    uint64_t r;
    asm("mov.b64 %0, {%1, %1};" : "=l"(r) : "f"(v));
    return r;
}
__device__ __forceinline__ uint64_t fma2(uint64_t a, uint64_t b, uint64_t c) {
    uint64_t d;
    asm("fma.rn.f32x2 %0, %1, %2, %3;" : "=l"(d) : "l"(a), "l"(b), "l"(c));
    return d;
}
__device__ __forceinline__ uint64_t mul2(uint64_t a, uint64_t b) {
    uint64_t d;
    asm("mul.rn.f32x2 %0, %1, %2;" : "=l"(d) : "l"(a), "l"(b));
    return d;
}
__device__ __forceinline__ uint64_t add2(uint64_t a, uint64_t b) {
    uint64_t d;
    asm("add.rn.f32x2 %0, %1, %2;" : "=l"(d) : "l"(a), "l"(b));
    return d;
}
__device__ __forceinline__ uint64_t lds64(uint32_t addr) {
    uint64_t d;
    asm("ld.shared.b64 %0, [%1];" : "=l"(d) : "r"(addr));
    return d;
}

__device__ __forceinline__ float cos_poly(float x) {
    // x in [0, pi]; cos(x) = -sin(x - pi/2). Degree-9 Taylor, |err| < 2.8e-6.
    float t = x - 1.57079632679489662f;
    float u = t * t;
    float p = fmaf(u, 2.75573192e-6f, -1.98412698e-4f);
    p = fmaf(u, p, 8.33333333e-3f);
    p = fmaf(u, p, -1.66666667e-1f);
    p = fmaf(u, p, 1.0f);
    return -t * p;
}

__global__ void __launch_bounds__(256)
quantum_parity_kernel(const float* __restrict__ x,
                      const float* __restrict__ W,
                      const float* __restrict__ bias,
                      float* __restrict__ out,
                      int nrows, int stride) {
    __shared__ float2 sW[NFEAT + 1];  // sW[f] = {W[0][f], W[1][f]}, sW[36] = bias
    int tid = threadIdx.x;
    int gid = blockIdx.x * 256 + tid;

    // Both rows' input loads issue back-to-back (4 independent LDG.128).
    int r0 = gid;
    int r1 = gid + stride;
    int c0i = r0 < nrows ? r0 : (nrows - 1);
    int c1i = r1 < nrows ? r1 : (nrows - 1);
    const float4* xp0 = reinterpret_cast<const float4*>(x) + (size_t)c0i * 2;
    const float4* xp1 = reinterpret_cast<const float4*>(x) + (size_t)c1i * 2;
    float4 a0 = xp0[0];
    float4 d0 = xp0[1];
    float4 a1 = xp1[0];
    float4 d1 = xp1[1];

    // W/bias -> shared, in flight during the cos math below.
    if (tid <= NFEAT) {
        float lo, hi;
        if (tid < NFEAT) { lo = W[tid];  hi = W[NFEAT + tid]; }
        else             { lo = bias[0]; hi = bias[1]; }
        sW[tid] = make_float2(lo, hi);
    }

    // 16 cosines (8 per row), duplicated into both f32x2 lanes.
    uint64_t c0[NQ], c1[NQ];
    c0[0] = pack_dup(cos_poly(a0.x));
    c1[0] = pack_dup(cos_poly(a1.x));
    c0[1] = pack_dup(cos_poly(a0.y));
    c1[1] = pack_dup(cos_poly(a1.y));
    c0[2] = pack_dup(cos_poly(a0.z));
    c1[2] = pack_dup(cos_poly(a1.z));
    c0[3] = pack_dup(cos_poly(a0.w));
    c1[3] = pack_dup(cos_poly(a1.w));
    c0[4] = pack_dup(cos_poly(d0.x));
    c1[4] = pack_dup(cos_poly(d1.x));
    c0[5] = pack_dup(cos_poly(d0.y));
    c1[5] = pack_dup(cos_poly(d1.y));
    c0[6] = pack_dup(cos_poly(d0.z));
    c1[6] = pack_dup(cos_poly(d1.z));
    c0[7] = pack_dup(cos_poly(d0.w));
    c1[7] = pack_dup(cos_poly(d1.w));

    __syncthreads();

    uint32_t sbase = (uint32_t)__cvta_generic_to_shared(sW);
    uint64_t bz = lds64(sbase + NFEAT * 8);

    // Per row: 2 independent accumulator chains. W slot loaded ONCE, used by
    // both rows.
    uint64_t accA0 = bz, accB0 = 0ull;   // row 0
    uint64_t accA1 = bz, accB1 = 0ull;   // row 1

    // Single-Z features: prefix products.
    uint64_t p0 = c0[0], p1 = c1[0];
    {
        uint64_t wv = lds64(sbase + 0);
        accA0 = fma2(wv, p0, accA0);
        accA1 = fma2(wv, p1, accA1);
    }
#pragma unroll
    for (int k = 1; k < NQ; k++) {
        p0 = mul2(p0, c0[k]);
        p1 = mul2(p1, c1[k]);
        uint64_t wv = lds64(sbase + k * 8);
        if (k & 1) { accB0 = fma2(wv, p0, accB0); accB1 = fma2(wv, p1, accB1); }
        else       { accA0 = fma2(wv, p0, accA0); accA1 = fma2(wv, p1, accA1); }
    }

    // Pair features: window products c_{i+1}..c_j.
    int f = NQ;
#pragma unroll
    for (int i = 0; i < NQ - 1; i++) {
        uint64_t q0 = c0[i + 1], q1 = c1[i + 1];
        {
            uint64_t wv = lds64(sbase + f * 8);
            if (f & 1) { accB0 = fma2(wv, q0, accB0); accB1 = fma2(wv, q1, accB1); }
            else       { accA0 = fma2(wv, q0, accA0); accA1 = fma2(wv, q1, accA1); }
            f++;
        }
#pragma unroll
        for (int j = i + 2; j < NQ; j++) {
            q0 = mul2(q0, c0[j]);
            q1 = mul2(q1, c1[j]);
            uint64_t wv = lds64(sbase + f * 8);
            if (f & 1) { accB0 = fma2(wv, q0, accB0); accB1 = fma2(wv, q1, accB1); }
            else       { accA0 = fma2(wv, q0, accA0); accA1 = fma2(wv, q1, accA1); }
            f++;
        }
    }

    uint64_t out0 = add2(accA0, accB0);
    uint64_t out1 = add2(accA1, accB1);

    if (r0 < nrows) reinterpret_cast<uint64_t*>(out)[r0] = out0;
    if (r1 < nrows) reinterpret_cast<uint64_t*>(out)[r1] = out1;
}

extern "C" void kernel_launch(void* const* d_in, const int* in_sizes, int n_in,
                              void* d_out, int out_size) {
    const float* x    = (const float*)d_in[0];   // (B, 8) fp32
    const float* W    = (const float*)d_in[1];   // (2, 36) fp32
    const float* bias = (const float*)d_in[2];   // (2,) fp32

    int nrows = in_sizes[0] / NQ;                // 131072
    float* out = (float*)d_out;                  // (B, 2) fp32

    int block = 256;
    int grid = (nrows + block * RPT - 1) / (block * RPT);  // 256
    int stride = grid * block;                             // 65536
    quantum_parity_kernel<<<grid, block>>>(x, W, bias, out, nrows, stride);
}